// round 16
// baseline (speedup 1.0000x reference)
#include <cuda_runtime.h>
#include <cstdint>

// IndexedLinearLayer: out[j] = sum_i W[idx[i], i, j] * x[i] + bias[j]
// x f32[8192], indices int32 OR int64 [8192] (dtype detected at runtime),
// param_index f32[16,8192,2048], bias f32[2048] -> out f32[2048]
//
// R16: 256-bit weight loads. ptxas (R9 error) confirmed ld.global .v8.b32
// with inline .L2::evict_last exists on sm_100a. Halves LDG count per byte
// (R15 showed gemv at 5.45 TB/s warm with issue/occ slack -> per-LDG L1tex
// wavefront overhead suspected as the binding cost).
//  - thread j-width 8 -> J_BLOCKS=1; I_PER_BLK 32->16 keeps grid at 512 CTAs.
//  - two v4-REDs/thread into NPART=8 slabs (64 collisions/addr, proven-safe).
//  - single-counter last-CTA fold (64 KB L2-resident, sub-us tail).

#define SIZE_IN    8192
#define SIZE_OUT   2048
#define NUM_Q      16
#define THREADS    256
#define I_PER_BLK  16
#define I_BLOCKS   (SIZE_IN / I_PER_BLK)      // 512 CTAs
#define NPART      8                          // partial-sum slabs

// Zero-initialized at module load; the fold re-zeroes/resets every call.
__device__ float    g_partial[NPART][SIZE_OUT];  // 64 KB
__device__ unsigned g_done;

__device__ __forceinline__ void ldg256_evict_last(const float* p, float* v) {
    uint32_t a0, a1, a2, a3, a4, a5, a6, a7;
    asm volatile(
        "ld.global.nc.L2::evict_last.v8.b32 {%0,%1,%2,%3,%4,%5,%6,%7}, [%8];"
        : "=r"(a0), "=r"(a1), "=r"(a2), "=r"(a3),
          "=r"(a4), "=r"(a5), "=r"(a6), "=r"(a7)
        : "l"(p));
    v[0] = __uint_as_float(a0); v[1] = __uint_as_float(a1);
    v[2] = __uint_as_float(a2); v[3] = __uint_as_float(a3);
    v[4] = __uint_as_float(a4); v[5] = __uint_as_float(a5);
    v[6] = __uint_as_float(a6); v[7] = __uint_as_float(a7);
}

__global__ __launch_bounds__(THREADS, 4)   // up to 64 regs/thread
void indexed_gemv_kernel(const float* __restrict__ x,
                         const void*  __restrict__ idx_raw,
                         const float* __restrict__ W,
                         const float* __restrict__ bias,
                         float*       __restrict__ out) {
    __shared__ float        s_x[I_PER_BLK];
    __shared__ const float* s_row[I_PER_BLK];
    __shared__ int          s_is64;
    __shared__ int          s_last;

    const int t  = threadIdx.x;
    const int i0 = blockIdx.x * I_PER_BLK;

    const long long* p64 = (const long long*)idx_raw;
    const int*       p32 = (const int*)idx_raw;

    // Dtype probe: first 16 int64-interpreted words (always in-bounds for
    // both int32[8192] and int64[8192]). Genuine int64 indices are all in
    // [0,16); int32 data reinterpreted is out of range w.p. 1-(1/16)^16.
    if (t < 32) {
        long long v = (t < 16) ? p64[t] : 0;
        int ok = (v >= 0 && v < NUM_Q);
        unsigned good = __ballot_sync(0xffffffffu, ok);
        if (t == 0) s_is64 = ((good & 0xFFFFu) == 0xFFFFu);
    }
    __syncthreads();

    // Stage the 16 (x, gathered-row-pointer) pairs for this i-chunk.
    if (t < I_PER_BLK) {
        const int i = i0 + t;
        s_x[t] = x[i];
        const int q = s_is64 ? (int)p64[i] : p32[i];
        s_row[t] = W + (size_t)q * ((size_t)SIZE_IN * SIZE_OUT)
                     + (size_t)i * SIZE_OUT;
    }
    __syncthreads();

    const int j0 = t * 8;   // 256 threads x 8 floats = 2048 = SIZE_OUT

    float acc[8] = {0.f, 0.f, 0.f, 0.f, 0.f, 0.f, 0.f, 0.f};

    // Fully-unrolled stream: one 256-bit evict_last load per i-row.
    #pragma unroll
    for (int k = 0; k < I_PER_BLK; ++k) {
        float w[8];
        ldg256_evict_last(s_row[k] + j0, w);
        const float xv = s_x[k];
        #pragma unroll
        for (int c = 0; c < 8; ++c)
            acc[c] = fmaf(w[c], xv, acc[c]);
    }

    // Split-K combine: two v4-REDs into one of 8 slabs (64 collisions/addr).
    float* dst = &g_partial[blockIdx.x & (NPART - 1)][j0];
    asm volatile("red.global.add.v4.f32 [%0], {%1, %2, %3, %4};"
                 :: "l"(dst), "f"(acc[0]), "f"(acc[1]), "f"(acc[2]), "f"(acc[3])
                 : "memory");
    asm volatile("red.global.add.v4.f32 [%0], {%1, %2, %3, %4};"
                 :: "l"(dst + 4), "f"(acc[4]), "f"(acc[5]), "f"(acc[6]), "f"(acc[7])
                 : "memory");

    // Last-CTA-done fold (single column now).
    __threadfence();
    if (t == 0) {
        unsigned old = atomicAdd(&g_done, 1u);
        s_last = (old == I_BLOCKS - 1);
    }
    __syncthreads();

    if (s_last) {
        __threadfence();   // observe all CTAs' slab REDs
        float4 sA = *reinterpret_cast<const float4*>(bias + j0);
        float4 sB = *reinterpret_cast<const float4*>(bias + j0 + 4);
        #pragma unroll
        for (int p = 0; p < NPART; ++p) {
            float4 vA = *reinterpret_cast<const float4*>(&g_partial[p][j0]);
            float4 vB = *reinterpret_cast<const float4*>(&g_partial[p][j0 + 4]);
            sA.x += vA.x; sA.y += vA.y; sA.z += vA.z; sA.w += vA.w;
            sB.x += vB.x; sB.y += vB.y; sB.z += vB.z; sB.w += vB.w;
            *reinterpret_cast<float4*>(&g_partial[p][j0]) =
                make_float4(0.f, 0.f, 0.f, 0.f);
            *reinterpret_cast<float4*>(&g_partial[p][j0 + 4]) =
                make_float4(0.f, 0.f, 0.f, 0.f);
        }
        *reinterpret_cast<float4*>(out + j0)     = sA;
        *reinterpret_cast<float4*>(out + j0 + 4) = sB;
        if (t == 0) g_done = 0;   // reset for next call
    }
}

extern "C" void kernel_launch(void* const* d_in, const int* in_sizes, int n_in,
                              void* d_out, int out_size) {
    // Map buffers by size where unique; x/indices keep metadata order.
    const float* x    = (const float*)d_in[0];
    const void*  idxp = d_in[1];
    const float* W    = (const float*)d_in[2];
    const float* bias = (const float*)d_in[3];
    for (int k = 0; k < n_in; ++k) {
        long long sz = in_sizes[k];
        if (sz == (long long)NUM_Q * SIZE_IN * SIZE_OUT) W    = (const float*)d_in[k];
        else if (sz == SIZE_OUT)                         bias = (const float*)d_in[k];
    }
    float* out = (float*)d_out;

    indexed_gemv_kernel<<<I_BLOCKS, THREADS>>>(x, idxp, W, bias, out);
}